// round 9
// baseline (speedup 1.0000x reference)
#include <cuda_runtime.h>
#include <cuda_fp16.h>
#include <cstdint>

#define B 512
#define HID 128
#define IN_DIM 595

#define TSTR 272            // tile row stride (bytes) -> conflict-free ldmatrix
#define TILE_BYTES 34816    // 128 rows * 272

// ---------------- device scratch (no allocations allowed) ----------------
__device__ float g_scratch[4 * B * HID];               // H1, H2, U, V
__device__ __align__(16) unsigned char g_bsw[34816];   // C^T staged fp16

// ======================= helpers =======================
__device__ __forceinline__ uint32_t smem_u32(const void* p) {
    uint32_t a;
    asm("{ .reg .u64 t; cvta.to.shared.u64 t, %1; cvt.u32.u64 %0, t; }" : "=r"(a) : "l"(p));
    return a;
}
__device__ __forceinline__ void ldm4(uint32_t* r, uint32_t addr) {
    asm volatile("ldmatrix.sync.aligned.m8n8.x4.shared.b16 {%0,%1,%2,%3}, [%4];"
                 : "=r"(r[0]), "=r"(r[1]), "=r"(r[2]), "=r"(r[3]) : "r"(addr));
}
__device__ __forceinline__ void mma_fp16(float* c, const uint32_t* a, uint32_t b0, uint32_t b1) {
    asm volatile(
        "mma.sync.aligned.m16n8k16.row.col.f32.f16.f16.f32 "
        "{%0,%1,%2,%3}, {%4,%5,%6,%7}, {%8,%9}, {%0,%1,%2,%3};"
        : "+f"(c[0]), "+f"(c[1]), "+f"(c[2]), "+f"(c[3])
        : "r"(a[0]), "r"(a[1]), "r"(a[2]), "r"(a[3]), "r"(b0), "r"(b1));
}

// ======================= encoder GEMM (K=595, 2 rows/block) =======================
__global__ __launch_bounds__(512) void enc_gemm(const float* __restrict__ X,
                                                const float* __restrict__ W,
                                                const float* __restrict__ bias,
                                                float* __restrict__ Y, int K, int doRelu) {
    __shared__ float Xs[2 * 608];
    __shared__ float red[3][2][128];
    const int tid = threadIdx.x;
    const int n = tid & 127, q = tid >> 7;
    const int m0 = blockIdx.x * 2;
    for (int idx = tid; idx < 2 * K; idx += 512) {
        int r = idx < K ? 0 : 1, k = idx < K ? idx : idx - K;
        Xs[r * 608 + k] = X[(m0 + r) * K + k];
    }
    __syncthreads();
    const int kb = (K * q) >> 2, ke = (K * (q + 1)) >> 2;
    float a0 = 0.f, a1 = 0.f;
    const float* Wn = W + n;
#pragma unroll 8
    for (int k = kb; k < ke; ++k) {
        float w = __ldg(Wn + k * 128);
        a0 = fmaf(Xs[k], w, a0);
        a1 = fmaf(Xs[608 + k], w, a1);
    }
    if (q) { red[q - 1][0][n] = a0; red[q - 1][1][n] = a1; }
    __syncthreads();
    if (q == 0) {
        float bv = bias ? bias[n] : 0.f;
        float r0 = a0 + red[0][0][n] + red[1][0][n] + red[2][0][n] + bv;
        float r1 = a1 + red[0][1][n] + red[1][1][n] + red[2][1][n] + bv;
        if (doRelu) { r0 = fmaxf(r0, 0.f); r1 = fmaxf(r1, 0.f); }
        Y[(m0 + 0) * 128 + n] = r0;
        Y[(m0 + 1) * 128 + n] = r1;
    }
}

// ======================= H2 GEMM (K=128, 4 rows/block) =======================
__global__ __launch_bounds__(512) void enc4(const float* __restrict__ X,
                                            const float* __restrict__ W,
                                            const float* __restrict__ bias,
                                            float* __restrict__ Y, int doRelu) {
    __shared__ float Xs[512];
    __shared__ float red[3][4][128];
    const int tid = threadIdx.x;
    const int n = tid & 127, q = tid >> 7;
    const int m0 = blockIdx.x * 4;
    Xs[tid] = X[m0 * 128 + tid];
    __syncthreads();
    float a0 = 0.f, a1 = 0.f, a2 = 0.f, a3 = 0.f;
    const float* Wn = W + n;
#pragma unroll 8
    for (int k = q * 32; k < q * 32 + 32; ++k) {
        float w = __ldg(Wn + k * 128);
        a0 = fmaf(Xs[k], w, a0);
        a1 = fmaf(Xs[128 + k], w, a1);
        a2 = fmaf(Xs[256 + k], w, a2);
        a3 = fmaf(Xs[384 + k], w, a3);
    }
    if (q) {
        red[q - 1][0][n] = a0; red[q - 1][1][n] = a1;
        red[q - 1][2][n] = a2; red[q - 1][3][n] = a3;
    }
    __syncthreads();
    if (q == 0) {
        float bv = bias ? bias[n] : 0.f;
        float r0 = a0 + red[0][0][n] + red[1][0][n] + red[2][0][n] + bv;
        float r1 = a1 + red[0][1][n] + red[1][1][n] + red[2][1][n] + bv;
        float r2 = a2 + red[0][2][n] + red[1][2][n] + red[2][2][n] + bv;
        float r3 = a3 + red[0][3][n] + red[1][3][n] + red[2][3][n] + bv;
        if (doRelu) {
            r0 = fmaxf(r0, 0.f); r1 = fmaxf(r1, 0.f);
            r2 = fmaxf(r2, 0.f); r3 = fmaxf(r3, 0.f);
        }
        Y[(m0 + 0) * 128 + n] = r0;
        Y[(m0 + 1) * 128 + n] = r1;
        Y[(m0 + 2) * 128 + n] = r2;
        Y[(m0 + 3) * 128 + n] = r3;
    }
}

// ======================= fused U+V GEMM (4 rows/block, 256 cols) =======================
// col < 128: U[m,col] = H2[m,:]@Wp1[0:128,col] + bp1[col]
// col >=128: V[m,col-128] = H2[m,:]@Wp1[128:256,col-128]
__global__ __launch_bounds__(512) void enc_uv4(const float* __restrict__ H2,
                                               const float* __restrict__ Wp1,
                                               const float* __restrict__ bp1,
                                               float* __restrict__ U, float* __restrict__ V) {
    __shared__ float Xs[512];
    __shared__ float red[4][256];
    const int tid = threadIdx.x;
    const int col = tid & 255, q = tid >> 8;   // q in {0,1}
    const int m0 = blockIdx.x * 4;
    Xs[tid] = H2[m0 * 128 + tid];
    __syncthreads();
    const float* Wc = (col < 128) ? (Wp1 + col) : (Wp1 + 128 * 128 + (col - 128));
    float a0 = 0.f, a1 = 0.f, a2 = 0.f, a3 = 0.f;
#pragma unroll 8
    for (int k = q * 64; k < q * 64 + 64; ++k) {
        float w = __ldg(Wc + k * 128);
        a0 = fmaf(Xs[k], w, a0);
        a1 = fmaf(Xs[128 + k], w, a1);
        a2 = fmaf(Xs[256 + k], w, a2);
        a3 = fmaf(Xs[384 + k], w, a3);
    }
    if (q) {
        red[0][col] = a0; red[1][col] = a1;
        red[2][col] = a2; red[3][col] = a3;
    }
    __syncthreads();
    if (q == 0) {
        float bv = (col < 128) ? bp1[col] : 0.f;
        float r0 = a0 + red[0][col] + bv;
        float r1 = a1 + red[1][col] + bv;
        float r2 = a2 + red[2][col] + bv;
        float r3 = a3 + red[3][col] + bv;
        float* dst = (col < 128) ? U : V;
        int c = col & 127;
        dst[(m0 + 0) * 128 + c] = r0;
        dst[(m0 + 1) * 128 + c] = r1;
        dst[(m0 + 2) * 128 + c] = r2;
        dst[(m0 + 3) * 128 + c] = r3;
    }
}

// ======================= prep: C^T fp16, staged layout =======================
__global__ void prep_C(const float* __restrict__ Wp1) {
    int idx = blockIdx.x * 256 + threadIdx.x;   // 16384 total
    int k = idx >> 7, d = idx & 127;
    float v = Wp1[(256 + d) * 128 + k];
    *(__half*)(g_bsw + (uint32_t)k * TSTR + d * 2) = __float2half_rn(v);
}

// ======================= pairwise kernel: 8 i per CTA, occ 2, 2 syncs/ii ===========
#define OFF_A   0
#define OFF_B   34816
#define OFF_HJ  69632
#define OFF_HIS 104448       // 8 * 256 B fp16
#define OFF_US  106496       // 8 * 512 B fp32
#define OFF_W2  110592
#define OFF_RED 111104
#define SMEM_PAIR 113152

__global__ __launch_bounds__(256, 2) void pair_mma(
    const float* __restrict__ H, const float* __restrict__ U, const float* __restrict__ V,
    const float* __restrict__ Wp2, const float* __restrict__ bp2, float* __restrict__ out) {
    extern __shared__ char sm[];
    const uint32_t sb = smem_u32(sm);
    float* w2  = (float*)(sm + OFF_W2);
    float* red = (float*)(sm + OFF_RED);

    const int tid  = threadIdx.x;
    const int lane = tid & 31, wid = tid >> 5;
    const int wm = wid & 1, wn = wid >> 1;     // warp tile: 64 j-rows x 32 k-cols
    const int i_base = blockIdx.x * 8;
    const int j0 = blockIdx.y * 128;

    // ---- stage B (C^T fp16, 34816 B = 2176 uint4) ----
    {
        const uint4* g = (const uint4*)g_bsw;
        uint4* s = (uint4*)(sm + OFF_B);
#pragma unroll
        for (int t = 0; t < 9; ++t) {
            int idx = tid + t * 256;
            if (idx < 2176) s[idx] = g[idx];
        }
    }
    const int j  = tid >> 1;
    const int dh = (tid & 1) << 6;

    // ---- stage HJ: fp16(h_j) tile ----
    {
        const float4* Hj = (const float4*)(H + (size_t)(j0 + j) * HID + dh);
        char* row = sm + OFF_HJ + (uint32_t)j * TSTR + dh * 2;
#pragma unroll
        for (int t = 0; t < 8; ++t) {
            float4 v0 = Hj[2 * t], v1 = Hj[2 * t + 1];
            __half2 a0 = __floats2half2_rn(v0.x, v0.y);
            __half2 a1 = __floats2half2_rn(v0.z, v0.w);
            __half2 a2 = __floats2half2_rn(v1.x, v1.y);
            __half2 a3 = __floats2half2_rn(v1.z, v1.w);
            uint4 o;
            o.x = *(uint32_t*)&a0; o.y = *(uint32_t*)&a1;
            o.z = *(uint32_t*)&a2; o.w = *(uint32_t*)&a3;
            *(uint4*)(row + t * 16) = o;
        }
    }
    // ---- stage his (fp16) and Us (fp32); w2 ----
    if (tid < 128) {
#pragma unroll
        for (int ii = 0; ii < 8; ++ii) {
            float hv = H[(size_t)(i_base + ii) * HID + tid];
            *(__half*)(sm + OFF_HIS + ii * 256 + tid * 2) = __float2half_rn(hv);
            *(float*)(sm + OFF_US + ii * 512 + tid * 4) = U[(size_t)(i_base + ii) * HID + tid];
        }
        w2[tid] = Wp2[tid];
    }

    const uint32_t aAddrBase = sb + OFF_A + (uint32_t)(wm * 64 + (lane & 15)) * TSTR + (lane >> 4) * 16;
    const uint32_t bAddrBase = sb + OFF_B + (uint32_t)(wn * 32 + (lane & 15)) * TSTR + (lane >> 4) * 16;
    const char* hjRow = sm + OFF_HJ + (uint32_t)j * TSTR + dh * 2;
    char* aRow = sm + OFF_A + (uint32_t)j * TSTR + dh * 2;
    const float b2v = bp2[0];
    const int kb = wn * 32;

    __syncthreads();

    for (int ii = 0; ii < 8; ++ii) {
        // ---- out-write of previous ii (reads red) overlapped with A-build ----
        if (ii > 0 && tid < 128) {
            float s = red[tid] + red[128 + tid] + red[256 + tid] + red[384 + tid] + b2v;
            out[(size_t)(i_base + ii - 1) * B + j0 + tid] = s;
        }
        // ---- build A: A[j][d] = |hj - hi| fp16 ----
        {
            const __half2* hi2 = (const __half2*)(sm + OFF_HIS + ii * 256 + dh * 2);
#pragma unroll
            for (int m = 0; m < 8; ++m) {
                uint4 hv = *(const uint4*)(hjRow + m * 16);
                __half2 j0h = *(__half2*)&hv.x, j1h = *(__half2*)&hv.y;
                __half2 j2h = *(__half2*)&hv.z, j3h = *(__half2*)&hv.w;
                __half2 t0 = __habs2(__hsub2(j0h, hi2[4 * m + 0]));
                __half2 t1 = __habs2(__hsub2(j1h, hi2[4 * m + 1]));
                __half2 t2 = __habs2(__hsub2(j2h, hi2[4 * m + 2]));
                __half2 t3 = __habs2(__hsub2(j3h, hi2[4 * m + 3]));
                uint4 o;
                o.x = *(uint32_t*)&t0; o.y = *(uint32_t*)&t1;
                o.z = *(uint32_t*)&t2; o.w = *(uint32_t*)&t3;
                *(uint4*)(aRow + m * 16) = o;
            }
        }
        __syncthreads();   // A ready; prev out-write done

        // ---- MMA: single-term fp16 ----
        float acc[4][4][4];
#pragma unroll
        for (int a = 0; a < 4; ++a)
#pragma unroll
            for (int b = 0; b < 4; ++b) {
                acc[a][b][0] = 0.f; acc[a][b][1] = 0.f;
                acc[a][b][2] = 0.f; acc[a][b][3] = 0.f;
            }
#pragma unroll
        for (int ks = 0; ks < 8; ++ks) {
            uint32_t af[4][4], bh[2][4];
#pragma unroll
            for (int mt = 0; mt < 4; ++mt)
                ldm4(af[mt], aAddrBase + mt * (16 * TSTR) + ks * 32);
#pragma unroll
            for (int p = 0; p < 2; ++p)
                ldm4(bh[p], bAddrBase + p * (16 * TSTR) + ks * 32);
#pragma unroll
            for (int mt = 0; mt < 4; ++mt)
#pragma unroll
                for (int nt = 0; nt < 4; ++nt)
                    mma_fp16(acc[mt][nt], af[mt],
                             bh[nt >> 1][nt & 1], bh[nt >> 1][(nt & 1) + 2]);
        }

        // ---- epilogue: relu(acc + U_i + V_j) . w2, partial k-sums to red ----
        const float* Usi = (const float*)(sm + OFF_US + ii * 512);
#pragma unroll
        for (int mt = 0; mt < 4; ++mt) {
            const int r0 = wm * 64 + mt * 16 + (lane >> 2);
            float p0 = 0.f, p1 = 0.f;
#pragma unroll
            for (int nt = 0; nt < 4; ++nt) {
                const int k = kb + nt * 8 + (lane & 3) * 2;
                float2 v0 = __ldg((const float2*)(V + (size_t)(j0 + r0) * HID + k));
                float2 v1 = __ldg((const float2*)(V + (size_t)(j0 + r0 + 8) * HID + k));
                float u0 = Usi[k], u1 = Usi[k + 1];
                float w0 = w2[k], w1 = w2[k + 1];
                p0 = fmaf(fmaxf(acc[mt][nt][0] + u0 + v0.x, 0.f), w0, p0);
                p0 = fmaf(fmaxf(acc[mt][nt][1] + u1 + v0.y, 0.f), w1, p0);
                p1 = fmaf(fmaxf(acc[mt][nt][2] + u0 + v1.x, 0.f), w0, p1);
                p1 = fmaf(fmaxf(acc[mt][nt][3] + u1 + v1.y, 0.f), w1, p1);
            }
            p0 += __shfl_down_sync(0xffffffffu, p0, 2, 4);
            p0 += __shfl_down_sync(0xffffffffu, p0, 1, 4);
            p1 += __shfl_down_sync(0xffffffffu, p1, 2, 4);
            p1 += __shfl_down_sync(0xffffffffu, p1, 1, 4);
            if ((lane & 3) == 0) {
                red[wn * 128 + r0]     = p0;
                red[wn * 128 + r0 + 8] = p1;
            }
        }
        __syncthreads();   // red complete (and A free for next build)
    }
    // final out-write
    if (tid < 128) {
        float s = red[tid] + red[128 + tid] + red[256 + tid] + red[384 + tid] + b2v;
        out[(size_t)(i_base + 7) * B + j0 + tid] = s;
    }
}

// ======================= launch =======================
extern "C" void kernel_launch(void* const* d_in, const int* in_sizes, int n_in,
                              void* d_out, int out_size) {
    const float* x   = (const float*)d_in[0];
    const float* W1  = (const float*)d_in[1];
    const float* b1  = (const float*)d_in[2];
    const float* W2  = (const float*)d_in[3];
    const float* b2  = (const float*)d_in[4];
    const float* Wp1 = (const float*)d_in[5];
    const float* bp1 = (const float*)d_in[6];
    const float* Wp2 = (const float*)d_in[7];
    const float* bp2 = (const float*)d_in[8];
    float* out = (float*)d_out;

    float* sp = nullptr;
    cudaGetSymbolAddress((void**)&sp, g_scratch);
    float* H1 = sp;
    float* H2 = sp + B * HID;
    float* U  = sp + 2 * B * HID;
    float* V  = sp + 3 * B * HID;

    prep_C<<<64, 256>>>(Wp1);
    enc_gemm<<<B / 2, 512>>>(x, W1, b1, H1, IN_DIM, 1);
    enc4<<<B / 4, 512>>>(H1, W2, b2, H2, 1);
    enc_uv4<<<B / 4, 512>>>(H2, Wp1, bp1, U, V);

    cudaFuncSetAttribute(pair_mma, cudaFuncAttributeMaxDynamicSharedMemorySize, SMEM_PAIR);
    dim3 grid(B / 8, B / 128);
    pair_mma<<<grid, 256, SMEM_PAIR>>>(H2, U, V, Wp2, bp2, out);
}

// round 10
// speedup vs baseline: 1.1050x; 1.1050x over previous
#include <cuda_runtime.h>
#include <cuda_fp16.h>
#include <cstdint>

#define B 512
#define HID 128
#define IN_DIM 595

#define TSTR 272            // tile row stride (bytes) -> conflict-free ldmatrix
#define TILE_BYTES 34816    // 128 rows * 272

// ---------------- device scratch (no allocations allowed) ----------------
__device__ float g_scratch[4 * B * HID];               // H1, H2, U, V
__device__ __align__(16) unsigned char g_bsw[34816];   // C^T staged fp16

// ======================= helpers =======================
__device__ __forceinline__ uint32_t smem_u32(const void* p) {
    uint32_t a;
    asm("{ .reg .u64 t; cvta.to.shared.u64 t, %1; cvt.u32.u64 %0, t; }" : "=r"(a) : "l"(p));
    return a;
}
__device__ __forceinline__ void ldm4(uint32_t* r, uint32_t addr) {
    asm volatile("ldmatrix.sync.aligned.m8n8.x4.shared.b16 {%0,%1,%2,%3}, [%4];"
                 : "=r"(r[0]), "=r"(r[1]), "=r"(r[2]), "=r"(r[3]) : "r"(addr));
}
__device__ __forceinline__ void mma_fp16(float* c, const uint32_t* a, uint32_t b0, uint32_t b1) {
    asm volatile(
        "mma.sync.aligned.m16n8k16.row.col.f32.f16.f16.f32 "
        "{%0,%1,%2,%3}, {%4,%5,%6,%7}, {%8,%9}, {%0,%1,%2,%3};"
        : "+f"(c[0]), "+f"(c[1]), "+f"(c[2]), "+f"(c[3])
        : "r"(a[0]), "r"(a[1]), "r"(a[2]), "r"(a[3]), "r"(b0), "r"(b1));
}

// ======================= encoder GEMM (K=595, 2 rows/block) =======================
__global__ __launch_bounds__(512) void enc_gemm(const float* __restrict__ X,
                                                const float* __restrict__ W,
                                                const float* __restrict__ bias,
                                                float* __restrict__ Y, int K, int doRelu) {
    __shared__ float Xs[2 * 608];
    __shared__ float red[3][2][128];
    const int tid = threadIdx.x;
    const int n = tid & 127, q = tid >> 7;
    const int m0 = blockIdx.x * 2;
    for (int idx = tid; idx < 2 * K; idx += 512) {
        int r = idx < K ? 0 : 1, k = idx < K ? idx : idx - K;
        Xs[r * 608 + k] = X[(m0 + r) * K + k];
    }
    __syncthreads();
    const int kb = (K * q) >> 2, ke = (K * (q + 1)) >> 2;
    float a0 = 0.f, a1 = 0.f;
    const float* Wn = W + n;
#pragma unroll 8
    for (int k = kb; k < ke; ++k) {
        float w = __ldg(Wn + k * 128);
        a0 = fmaf(Xs[k], w, a0);
        a1 = fmaf(Xs[608 + k], w, a1);
    }
    if (q) { red[q - 1][0][n] = a0; red[q - 1][1][n] = a1; }
    __syncthreads();
    if (q == 0) {
        float bv = bias ? bias[n] : 0.f;
        float r0 = a0 + red[0][0][n] + red[1][0][n] + red[2][0][n] + bv;
        float r1 = a1 + red[0][1][n] + red[1][1][n] + red[2][1][n] + bv;
        if (doRelu) { r0 = fmaxf(r0, 0.f); r1 = fmaxf(r1, 0.f); }
        Y[(m0 + 0) * 128 + n] = r0;
        Y[(m0 + 1) * 128 + n] = r1;
    }
}

// ======================= fused rest-of-encoder + prep =======================
// blocks [0,512): row m — h2 = relu(H1[m]@W2 + b2); U[m] = h2@A + bp1; V[m] = h2@Bm.
// blocks [512,544): stage C^T fp16 into g_bsw (16384 elems, 512/block).
__global__ __launch_bounds__(512) void enc_rest(const float* __restrict__ H1,
                                                const float* __restrict__ W2,
                                                const float* __restrict__ b2,
                                                const float* __restrict__ Wp1,
                                                const float* __restrict__ bp1,
                                                float* __restrict__ H2,
                                                float* __restrict__ U, float* __restrict__ V) {
    const int tid = threadIdx.x;
    const int bx = blockIdx.x;
    if (bx >= 512) {
        int idx = (bx - 512) * 512 + tid;           // < 16384
        int k = idx >> 7, d = idx & 127;
        float v = Wp1[(256 + d) * 128 + k];
        *(__half*)(g_bsw + (uint32_t)k * TSTR + d * 2) = __float2half_rn(v);
        return;
    }
    __shared__ float h1s[128], h2s[128];
    __shared__ float red[3][128];
    __shared__ float red2[256];
    const int m = bx;
    const int n = tid & 127, q = tid >> 7;          // 4-way K split
    if (tid < 128) h1s[tid] = H1[m * 128 + tid];
    __syncthreads();

    // stage B: h2
    {
        float a = 0.f;
        const float* Wn = W2 + n;
#pragma unroll 8
        for (int k = q * 32; k < q * 32 + 32; ++k)
            a = fmaf(h1s[k], __ldg(Wn + k * 128), a);
        if (q) red[q - 1][n] = a;
        __syncthreads();
        if (q == 0) {
            float r = fmaxf(a + red[0][n] + red[1][n] + red[2][n] + b2[n], 0.f);
            h2s[n] = r;
            H2[m * 128 + n] = r;
        }
        __syncthreads();
    }

    // stage C: U and V together (256 cols, 2-way K split)
    {
        const int col = tid & 255, q2 = tid >> 8;
        const float* Wc = (col < 128) ? (Wp1 + col) : (Wp1 + 128 * 128 + (col - 128));
        float a = 0.f;
#pragma unroll 8
        for (int k = q2 * 64; k < q2 * 64 + 64; ++k)
            a = fmaf(h2s[k], __ldg(Wc + k * 128), a);
        if (q2) red2[col] = a;
        __syncthreads();
        if (q2 == 0) {
            float r = a + red2[col] + (col < 128 ? bp1[col] : 0.f);
            float* dst = (col < 128) ? U : V;
            dst[m * 128 + (col & 127)] = r;
        }
    }
}

// ======================= pairwise kernel: 8 i per CTA, occ 2 (round-8 exact) ========
#define OFF_A   0
#define OFF_B   34816
#define OFF_HJ  69632
#define OFF_HIS 104448       // 8 * 256 B fp16
#define OFF_US  106496       // 8 * 512 B fp32
#define OFF_W2  110592
#define OFF_RED 111104
#define SMEM_PAIR 113152

__global__ __launch_bounds__(256, 2) void pair_mma(
    const float* __restrict__ H, const float* __restrict__ U, const float* __restrict__ V,
    const float* __restrict__ Wp2, const float* __restrict__ bp2, float* __restrict__ out) {
    extern __shared__ char sm[];
    const uint32_t sb = smem_u32(sm);
    float* w2  = (float*)(sm + OFF_W2);
    float* red = (float*)(sm + OFF_RED);

    const int tid  = threadIdx.x;
    const int lane = tid & 31, wid = tid >> 5;
    const int wm = wid & 1, wn = wid >> 1;     // warp tile: 64 j-rows x 32 k-cols
    const int i_base = blockIdx.x * 8;
    const int j0 = blockIdx.y * 128;

    // ---- stage B (C^T fp16, 34816 B = 2176 uint4) ----
    {
        const uint4* g = (const uint4*)g_bsw;
        uint4* s = (uint4*)(sm + OFF_B);
#pragma unroll
        for (int t = 0; t < 9; ++t) {
            int idx = tid + t * 256;
            if (idx < 2176) s[idx] = g[idx];
        }
    }
    const int j  = tid >> 1;
    const int dh = (tid & 1) << 6;

    // ---- stage HJ: fp16(h_j) tile ----
    {
        const float4* Hj = (const float4*)(H + (size_t)(j0 + j) * HID + dh);
        char* row = sm + OFF_HJ + (uint32_t)j * TSTR + dh * 2;
#pragma unroll
        for (int t = 0; t < 8; ++t) {
            float4 v0 = Hj[2 * t], v1 = Hj[2 * t + 1];
            __half2 a0 = __floats2half2_rn(v0.x, v0.y);
            __half2 a1 = __floats2half2_rn(v0.z, v0.w);
            __half2 a2 = __floats2half2_rn(v1.x, v1.y);
            __half2 a3 = __floats2half2_rn(v1.z, v1.w);
            uint4 o;
            o.x = *(uint32_t*)&a0; o.y = *(uint32_t*)&a1;
            o.z = *(uint32_t*)&a2; o.w = *(uint32_t*)&a3;
            *(uint4*)(row + t * 16) = o;
        }
    }
    // ---- stage his (fp16) and Us (fp32); w2 ----
    if (tid < 128) {
#pragma unroll
        for (int ii = 0; ii < 8; ++ii) {
            float hv = H[(size_t)(i_base + ii) * HID + tid];
            *(__half*)(sm + OFF_HIS + ii * 256 + tid * 2) = __float2half_rn(hv);
            *(float*)(sm + OFF_US + ii * 512 + tid * 4) = U[(size_t)(i_base + ii) * HID + tid];
        }
        w2[tid] = Wp2[tid];
    }
    __syncthreads();

    const uint32_t aAddrBase = sb + OFF_A + (uint32_t)(wm * 64 + (lane & 15)) * TSTR + (lane >> 4) * 16;
    const uint32_t bAddrBase = sb + OFF_B + (uint32_t)(wn * 32 + (lane & 15)) * TSTR + (lane >> 4) * 16;
    const char* hjRow = sm + OFF_HJ + (uint32_t)j * TSTR + dh * 2;
    char* aRow = sm + OFF_A + (uint32_t)j * TSTR + dh * 2;
    const float b2v = bp2[0];
    const int kb = wn * 32;

    for (int ii = 0; ii < 8; ++ii) {
        // ---- build A: A[j][d] = |hj - hi| fp16 ----
        {
            const __half2* hi2 = (const __half2*)(sm + OFF_HIS + ii * 256 + dh * 2);
#pragma unroll
            for (int m = 0; m < 8; ++m) {
                uint4 hv = *(const uint4*)(hjRow + m * 16);
                __half2 j0h = *(__half2*)&hv.x, j1h = *(__half2*)&hv.y;
                __half2 j2h = *(__half2*)&hv.z, j3h = *(__half2*)&hv.w;
                __half2 t0 = __habs2(__hsub2(j0h, hi2[4 * m + 0]));
                __half2 t1 = __habs2(__hsub2(j1h, hi2[4 * m + 1]));
                __half2 t2 = __habs2(__hsub2(j2h, hi2[4 * m + 2]));
                __half2 t3 = __habs2(__hsub2(j3h, hi2[4 * m + 3]));
                uint4 o;
                o.x = *(uint32_t*)&t0; o.y = *(uint32_t*)&t1;
                o.z = *(uint32_t*)&t2; o.w = *(uint32_t*)&t3;
                *(uint4*)(aRow + m * 16) = o;
            }
        }
        __syncthreads();

        // ---- MMA: single-term fp16 ----
        float acc[4][4][4];
#pragma unroll
        for (int a = 0; a < 4; ++a)
#pragma unroll
            for (int b = 0; b < 4; ++b) {
                acc[a][b][0] = 0.f; acc[a][b][1] = 0.f;
                acc[a][b][2] = 0.f; acc[a][b][3] = 0.f;
            }
#pragma unroll
        for (int ks = 0; ks < 8; ++ks) {
            uint32_t af[4][4], bh[2][4];
#pragma unroll
            for (int mt = 0; mt < 4; ++mt)
                ldm4(af[mt], aAddrBase + mt * (16 * TSTR) + ks * 32);
#pragma unroll
            for (int p = 0; p < 2; ++p)
                ldm4(bh[p], bAddrBase + p * (16 * TSTR) + ks * 32);
#pragma unroll
            for (int mt = 0; mt < 4; ++mt)
#pragma unroll
                for (int nt = 0; nt < 4; ++nt)
                    mma_fp16(acc[mt][nt], af[mt],
                             bh[nt >> 1][nt & 1], bh[nt >> 1][(nt & 1) + 2]);
        }

        // ---- epilogue: relu(acc + U_i + V_j) . w2, reduce over k ----
        const float* Usi = (const float*)(sm + OFF_US + ii * 512);
#pragma unroll
        for (int mt = 0; mt < 4; ++mt) {
            const int r0 = wm * 64 + mt * 16 + (lane >> 2);
            float p0 = 0.f, p1 = 0.f;
#pragma unroll
            for (int nt = 0; nt < 4; ++nt) {
                const int k = kb + nt * 8 + (lane & 3) * 2;
                float2 v0 = __ldg((const float2*)(V + (size_t)(j0 + r0) * HID + k));
                float2 v1 = __ldg((const float2*)(V + (size_t)(j0 + r0 + 8) * HID + k));
                float u0 = Usi[k], u1 = Usi[k + 1];
                float w0 = w2[k], w1 = w2[k + 1];
                p0 = fmaf(fmaxf(acc[mt][nt][0] + u0 + v0.x, 0.f), w0, p0);
                p0 = fmaf(fmaxf(acc[mt][nt][1] + u1 + v0.y, 0.f), w1, p0);
                p1 = fmaf(fmaxf(acc[mt][nt][2] + u0 + v1.x, 0.f), w0, p1);
                p1 = fmaf(fmaxf(acc[mt][nt][3] + u1 + v1.y, 0.f), w1, p1);
            }
            p0 += __shfl_down_sync(0xffffffffu, p0, 2, 4);
            p0 += __shfl_down_sync(0xffffffffu, p0, 1, 4);
            p1 += __shfl_down_sync(0xffffffffu, p1, 2, 4);
            p1 += __shfl_down_sync(0xffffffffu, p1, 1, 4);
            if ((lane & 3) == 0) {
                red[wn * 128 + r0]     = p0;
                red[wn * 128 + r0 + 8] = p1;
            }
        }
        __syncthreads();
        if (tid < 128) {
            float s = red[tid] + red[128 + tid] + red[256 + tid] + red[384 + tid] + b2v;
            out[(size_t)(i_base + ii) * B + j0 + tid] = s;
        }
        __syncthreads();
    }
}

// ======================= launch =======================
extern "C" void kernel_launch(void* const* d_in, const int* in_sizes, int n_in,
                              void* d_out, int out_size) {
    const float* x   = (const float*)d_in[0];
    const float* W1  = (const float*)d_in[1];
    const float* b1  = (const float*)d_in[2];
    const float* W2  = (const float*)d_in[3];
    const float* b2  = (const float*)d_in[4];
    const float* Wp1 = (const float*)d_in[5];
    const float* bp1 = (const float*)d_in[6];
    const float* Wp2 = (const float*)d_in[7];
    const float* bp2 = (const float*)d_in[8];
    float* out = (float*)d_out;

    float* sp = nullptr;
    cudaGetSymbolAddress((void**)&sp, g_scratch);
    float* H1 = sp;
    float* H2 = sp + B * HID;
    float* U  = sp + 2 * B * HID;
    float* V  = sp + 3 * B * HID;

    enc_gemm<<<B / 2, 512>>>(x, W1, b1, H1, IN_DIM, 1);
    enc_rest<<<B + 32, 512>>>(H1, W2, b2, Wp1, bp1, H2, U, V);

    cudaFuncSetAttribute(pair_mma, cudaFuncAttributeMaxDynamicSharedMemorySize, SMEM_PAIR);
    dim3 grid(B / 8, B / 128);
    pair_mma<<<grid, 256, SMEM_PAIR>>>(H2, U, V, Wp2, bp2, out);
}